// round 5
// baseline (speedup 1.0000x reference)
#include <cuda_runtime.h>
#include <stdint.h>
#include <math.h>

#define JAX_PARTITIONABLE 1

#define NROWS   65536
#define TSTEPS  12
#define WPB     8          // warps per block
#define THREADS 256
#define NBLOCKS 148        // 1 CTA/SM, persistent group loop
#define RPW     8          // rows per warp

// output layout (float32): seq | ent | logp | cnt | lengths | mask
#define OFF_ENT  (NROWS * TSTEPS)
#define OFF_LP   (2 * NROWS * TSTEPS)
#define OFF_CNT  (3 * NROWS * TSTEPS)
#define OFF_LEN  (OFF_CNT + NROWS)
#define OFF_MASK (OFF_LEN + NROWS)

// shared layout in float (4B) slots
#define SM_WH    0          // 128x128 = 16384
#define SM_WX    16384      // 32x128  =  4096
#define SM_WP    20480      // 128x16  =  2048
#define SM_B     22528      // 128
#define SM_BP    22656      // 16
#define SM_IN0   22672      // 32
#define SM_H0    22704      // 128
#define SM_KEY   22832      // 24 u32
#define SM_HS    22856      // WPB * 8 rows * 128 = 8192
#define SM_SEQ   31048      // WPB * 8 * 12 (int) = 768
#define SM_ST    31816      // WPB * 8 * 8  (int) = 512
#define SM_TOTF  32328      // 129312 bytes

__device__ __forceinline__ uint32_t rotl32(uint32_t x, int n) {
    return (x << n) | (x >> (32 - n));
}

// Threefry-2x32, 20 rounds (exact JAX cipher)
__device__ __forceinline__ void tf2x32(uint32_t k0, uint32_t k1,
                                       uint32_t &x0, uint32_t &x1) {
    uint32_t k2 = k0 ^ k1 ^ 0x1BD11BDAu;
    x0 += k0; x1 += k1;
#define TFR(r) { x0 += x1; x1 = rotl32(x1, (r)); x1 ^= x0; }
    TFR(13) TFR(15) TFR(26) TFR(6)
    x0 += k1; x1 += k2 + 1u;
    TFR(17) TFR(29) TFR(16) TFR(24)
    x0 += k2; x1 += k0 + 2u;
    TFR(13) TFR(15) TFR(26) TFR(6)
    x0 += k0; x1 += k1 + 3u;
    TFR(17) TFR(29) TFR(16) TFR(24)
    x0 += k1; x1 += k2 + 4u;
    TFR(13) TFR(15) TFR(26) TFR(6)
    x0 += k2; x1 += k0 + 5u;
#undef TFR
}

__device__ __forceinline__ uint32_t gbits(uint32_t k0, uint32_t k1, uint32_t idx) {
#if JAX_PARTITIONABLE
    uint32_t a = 0u, b = idx;
    tf2x32(k0, k1, a, b);
    return a ^ b;
#else
    const uint32_t half = (uint32_t)(NROWS * 16) / 2u;
    if (idx < half) {
        uint32_t a = idx, b = idx + half;
        tf2x32(k0, k1, a, b);
        return a;
    } else {
        uint32_t a = idx - half, b = idx;
        tf2x32(k0, k1, a, b);
        return b;
    }
#endif
}

__global__ void __launch_bounds__(THREADS, 1)
eq_sampler(const float* __restrict__ in0, const float* __restrict__ h0,
           const float* __restrict__ Wx, const float* __restrict__ Wh,
           const float* __restrict__ b,  const float* __restrict__ Wp,
           const float* __restrict__ bp, float* __restrict__ out) {
    extern __shared__ float sm[];
    int* smi = (int*)sm;
    const int tid = threadIdx.x;

    for (int i = tid; i < 16384; i += THREADS) sm[SM_WH + i] = Wh[i];
    for (int i = tid; i < 4096;  i += THREADS) sm[SM_WX + i] = Wx[i];
    for (int i = tid; i < 2048;  i += THREADS) sm[SM_WP + i] = Wp[i];
    if (tid < 128) sm[SM_B  + tid] = b[tid];
    if (tid < 16)  sm[SM_BP + tid] = bp[tid];
    if (tid < 32)  sm[SM_IN0 + tid] = in0[tid];
    if (tid < 128) sm[SM_H0 + tid] = h0[tid];

    if (tid == 0) {
        uint32_t* kp = (uint32_t*)(sm + SM_KEY);
#if JAX_PARTITIONABLE
        for (int t = 0; t < TSTEPS; t++) {
            uint32_t a = 0u, bb = (uint32_t)t;
            tf2x32(0u, 42u, a, bb);
            kp[2 * t] = a; kp[2 * t + 1] = bb;
        }
#else
        uint32_t ov[24];
        for (int j = 0; j < 12; j++) {
            uint32_t a = (uint32_t)j, bb = (uint32_t)(j + 12);
            tf2x32(0u, 42u, a, bb);
            ov[j] = a; ov[12 + j] = bb;
        }
        for (int t = 0; t < TSTEPS; t++) { kp[2 * t] = ov[2 * t]; kp[2 * t + 1] = ov[2 * t + 1]; }
#endif
    }
    __syncthreads();

    const int wid  = tid >> 5;
    const int lane = tid & 31;
    const float NEG_INF = __int_as_float(0xff800000);

    float* hbase = sm + SM_HS + wid * (RPW * 128);     // 8 rows x 128
    float4* hb4  = (float4*)hbase;
    int* seqw = smi + SM_SEQ + wid * (RPW * 12);       // 8 rows x 12
    int* stw  = smi + SM_ST  + wid * (RPW * 8);        // 8 rows x {cnt,ln,act,hasvar,len,ps0,ps1,pad}

    const int g  = lane >> 4;        // half-warp group
    const int tk = lane & 15;        // token id this lane evaluates
    // half g handles rows {g, 2+g, 4+g, 6+g} as 4 register streams

    // t=0 input projection (identical for all rows)
    float xw0[4];
#pragma unroll
    for (int v = 0; v < 4; v++) {
        float s = 0.0f;
#pragma unroll
        for (int k = 0; k < 32; k++)
            s = fmaf(sm[SM_IN0 + k], sm[SM_WX + k * 128 + lane * 4 + v], s);
        xw0[v] = s;
    }
    float bvec[4];
    *(float4*)bvec = ((const float4*)(sm + SM_B))[lane];
    const float4 hinit = ((const float4*)(sm + SM_H0))[lane];

    const int totalWarps = gridDim.x * WPB;
    for (int grp = blockIdx.x * WPB + wid; grp < NROWS / RPW; grp += totalWarps) {
        const int rowBase = grp * RPW;

        // ---- init group ----
#pragma unroll
        for (int r = 0; r < RPW; r++) hb4[r * 32 + lane] = hinit;
        if (lane < RPW) {
            int* st = stw + lane * 8;
            st[0] = 1; st[1] = 0; st[2] = 1; st[3] = 0; st[4] = 1; st[5] = -1; st[6] = -1;
            out[OFF_MASK + (size_t)(rowBase + lane) * 13] = 1.0f;
        }
        __syncwarp();

        for (int t = 0; t < TSTEPS; t++) {
            const uint32_t k0 = ((uint32_t*)(sm + SM_KEY))[2 * t];
            const uint32_t k1 = ((uint32_t*)(sm + SM_KEY))[2 * t + 1];

            // ---- x @ Wx (one-hot gather for t>0) ----
            float xw[RPW][4];
            if (t == 0) {
#pragma unroll
                for (int r = 0; r < RPW; r++) {
                    xw[r][0] = xw0[0]; xw[r][1] = xw0[1];
                    xw[r][2] = xw0[2]; xw[r][3] = xw0[3];
                }
            } else {
#pragma unroll
                for (int r = 0; r < RPW; r++) {
                    int p0 = stw[r * 8 + 5];
                    int p1 = stw[r * 8 + 6];
                    float4 a = make_float4(0.f, 0.f, 0.f, 0.f);
                    float4 c = make_float4(0.f, 0.f, 0.f, 0.f);
                    if (p0 >= 0) a = ((const float4*)(sm + SM_WX))[p0 * 32 + lane];
                    if (p1 >= 0) c = ((const float4*)(sm + SM_WX))[(16 + p1) * 32 + lane];
                    xw[r][0] = a.x + c.x; xw[r][1] = a.y + c.y;
                    xw[r][2] = a.z + c.z; xw[r][3] = a.w + c.w;
                }
            }

            // ---- h @ Wh : 8 rows, 4 outputs per lane ----
            {
                float acc[RPW][4];
#pragma unroll
                for (int r = 0; r < RPW; r++) {
                    acc[r][0] = 0.f; acc[r][1] = 0.f; acc[r][2] = 0.f; acc[r][3] = 0.f;
                }
                const float4* Wh4 = (const float4*)sm;  // SM_WH == 0
#pragma unroll 2
                for (int k4 = 0; k4 < 32; k4++) {
                    float hv[RPW][4];
#pragma unroll
                    for (int r = 0; r < RPW; r++)
                        *(float4*)hv[r] = hb4[r * 32 + k4];
#pragma unroll
                    for (int kk = 0; kk < 4; kk++) {
                        float4 w = Wh4[(k4 * 4 + kk) * 32 + lane];
#pragma unroll
                        for (int r = 0; r < RPW; r++) {
                            acc[r][0] = fmaf(hv[r][kk], w.x, acc[r][0]);
                            acc[r][1] = fmaf(hv[r][kk], w.y, acc[r][1]);
                            acc[r][2] = fmaf(hv[r][kk], w.z, acc[r][2]);
                            acc[r][3] = fmaf(hv[r][kk], w.w, acc[r][3]);
                        }
                    }
                }
                __syncwarp();
                // h_new = tanh((x@Wx + h@Wh) + b)
#pragma unroll
                for (int r = 0; r < RPW; r++) {
                    float4 hn;
                    hn.x = tanhf((xw[r][0] + acc[r][0]) + bvec[0]);
                    hn.y = tanhf((xw[r][1] + acc[r][1]) + bvec[1]);
                    hn.z = tanhf((xw[r][2] + acc[r][2]) + bvec[2]);
                    hn.w = tanhf((xw[r][3] + acc[r][3]) + bvec[3]);
                    hb4[r * 32 + lane] = hn;
                }
                __syncwarp();
            }

            // ---- logits: lane evaluates token tk for 4 rows (streams) ----
            float lg[4];
            {
                float accl[4] = {0.f, 0.f, 0.f, 0.f};
#pragma unroll 4
                for (int k4 = 0; k4 < 32; k4++) {
                    float hs[4][4];
#pragma unroll
                    for (int s = 0; s < 4; s++)
                        *(float4*)hs[s] = ((const float4*)(hbase + (2 * s + g) * 128))[k4];
#pragma unroll
                    for (int kk = 0; kk < 4; kk++) {
                        float wp = sm[SM_WP + (k4 * 4 + kk) * 16 + tk];
#pragma unroll
                        for (int s = 0; s < 4; s++)
                            accl[s] = fmaf(hs[s][kk], wp, accl[s]);
                    }
                }
                float bpt = sm[SM_BP + tk];
#pragma unroll
                for (int s = 0; s < 4; s++) lg[s] = accl[s] + bpt;
            }

            // ---- constraints (PRE-update state) ----
            bool ok[4];
#pragma unroll
            for (int s = 0; s < 4; s++) {
                int r = 2 * s + g;
                int cnt = stw[r * 8 + 0], ln = stw[r * 8 + 1], hv = stw[r * 8 + 3];
                int cl = cnt + ln;
                bool o = true;
                if (tk >= 8 && cl < 2) o = false;
                if (tk <  8 && cl > TSTEPS - 2) o = false;
                if (tk == 8 && cnt == 1 && hv == 0) o = false;
                ok[s] = o;
            }

            // ---- exact two-stage softmax + mask + renorm (16-lane reductions) ----
            float mx[4];
#pragma unroll
            for (int s = 0; s < 4; s++) mx[s] = lg[s];
#pragma unroll
            for (int d = 1; d < 16; d <<= 1)
#pragma unroll
                for (int s = 0; s < 4; s++)
                    mx[s] = fmaxf(mx[s], __shfl_xor_sync(0xffffffffu, mx[s], d));
            float ex[4], z[4];
#pragma unroll
            for (int s = 0; s < 4; s++) { ex[s] = expf(lg[s] - mx[s]); z[s] = ex[s]; }
#pragma unroll
            for (int d = 1; d < 16; d <<= 1)
#pragma unroll
                for (int s = 0; s < 4; s++)
                    z[s] += __shfl_xor_sync(0xffffffffu, z[s], d);
            float pm[4], ssum[4];
#pragma unroll
            for (int s = 0; s < 4; s++) { pm[s] = ok[s] ? (ex[s] / z[s]) : 0.0f; ssum[s] = pm[s]; }
#pragma unroll
            for (int d = 1; d < 16; d <<= 1)
#pragma unroll
                for (int s = 0; s < 4; s++)
                    ssum[s] += __shfl_xor_sync(0xffffffffu, ssum[s], d);
            float p[4], logp[4];
            bool pos[4];
#pragma unroll
            for (int s = 0; s < 4; s++) {
                p[s] = pm[s] / ssum[s];
                pos[s] = p[s] > 0.0f;
                logp[s] = pos[s] ? logf(p[s]) : NEG_INF;
            }

            // ---- gumbel noise (exact threefry bits) ----
            float sc[4];
#pragma unroll
            for (int s = 0; s < 4; s++) {
                uint32_t idx = ((uint32_t)(rowBase + 2 * s + g)) * 16u + (uint32_t)tk;
                uint32_t bts = gbits(k0, k1, idx);
                float f = __uint_as_float((bts >> 9) | 0x3f800000u) - 1.0f;
                float u = (f == 0.0f) ? 1.17549435e-38f : f;
                float gu = -logf(-logf(u));
                sc[s] = pos[s] ? (logp[s] + gu) : NEG_INF;
            }

            // ---- argmax over 16 tokens (first-index tie-break) ----
            float bs[4];
            int bi[4];
#pragma unroll
            for (int s = 0; s < 4; s++) { bs[s] = sc[s]; bi[s] = tk; }
#pragma unroll
            for (int d = 1; d < 16; d <<= 1) {
#pragma unroll
                for (int s = 0; s < 4; s++) {
                    float os = __shfl_xor_sync(0xffffffffu, bs[s], d);
                    int   oi = __shfl_xor_sync(0xffffffffu, bi[s], d);
                    if (os > bs[s] || (os == bs[s] && oi < bi[s])) { bs[s] = os; bi[s] = oi; }
                }
            }

            // ---- entropy ----
            float et[4];
#pragma unroll
            for (int s = 0; s < 4; s++) et[s] = pos[s] ? p[s] * logp[s] : 0.0f;
#pragma unroll
            for (int d = 1; d < 16; d <<= 1)
#pragma unroll
                for (int s = 0; s < 4; s++)
                    et[s] += __shfl_xor_sync(0xffffffffu, et[s], d);

            // ---- logp at sampled token ----
            float lp[4];
#pragma unroll
            for (int s = 0; s < 4; s++)
                lp[s] = __shfl_sync(0xffffffffu, logp[s], (lane & 16) + bi[s]);

            // ---- writer lanes (0 and 16): state update + parent/sibling ----
            if (tk == 0) {
#pragma unroll
                for (int s = 0; s < 4; s++) {
                    int r   = 2 * s + g;
                    int tok = bi[s];
                    int* st = stw + r * 8;
                    int row = rowBase + r;

                    seqw[r * 12 + t] = tok;
                    int ar  = (tok < 4) ? 2 : ((tok < 8) ? 1 : 0);
                    int cnt = st[0] - 1 + ar;
                    int ln  = st[1] + 1;
                    int act = (cnt > 0) && st[2];
                    st[0] = cnt; st[1] = ln; st[2] = act;
                    st[3] = st[3] | (tok >= 9);
                    st[4] += act;

                    out[(size_t)row * 12 + t]            = (float)tok;
                    out[OFF_ENT + (size_t)row * 12 + t]  = -et[s];
                    out[OFF_LP  + (size_t)row * 12 + t]  = lp[s];
                    out[OFF_MASK + (size_t)row * 13 + 1 + t] = act ? 1.0f : 0.0f;

                    int ps0, ps1;
                    if (tok < 8) {
                        ps0 = tok; ps1 = -1;
                    } else {
                        ps0 = -1; ps1 = -1;
                        int c = 0;
                        bool found = false;
                        for (int i = t; i >= 0; i--) {
                            int tk2 = seqw[r * 12 + i];
                            int a2 = (tk2 >= 0 && tk2 < 4) ? 2 : ((tk2 >= 4 && tk2 < 8) ? 1 : 0);
                            c += a2 - 1;
                            if (!found && c == 0) {
                                ps0 = tk2;
                                ps1 = (i + 1 < TSTEPS) ? seqw[r * 12 + i + 1] : -1;
                                found = true;
                            }
                        }
                    }
                    st[5] = ps0; st[6] = ps1;
                }
            }
            __syncwarp();
        }

        // ---- finalize group: cnt + lengths ----
        if (lane < RPW) {
            out[OFF_CNT + rowBase + lane] = (float)stw[lane * 8 + 0];
            out[OFF_LEN + rowBase + lane] = (float)stw[lane * 8 + 4];
        }
        __syncwarp();
    }
}

extern "C" void kernel_launch(void* const* d_in, const int* in_sizes, int n_in,
                              void* d_out, int out_size) {
    int base = (in_sizes[0] == 1) ? 1 : 0;
    const float* in0 = (const float*)d_in[base + 0];
    const float* h0  = (const float*)d_in[base + 1];
    const float* Wx  = (const float*)d_in[base + 2];
    const float* Wh  = (const float*)d_in[base + 3];
    const float* b   = (const float*)d_in[base + 4];
    const float* Wp  = (const float*)d_in[base + 5];
    const float* bp  = (const float*)d_in[base + 6];

    size_t smem = (size_t)SM_TOTF * sizeof(float);
    cudaFuncSetAttribute(eq_sampler, cudaFuncAttributeMaxDynamicSharedMemorySize, (int)smem);
    eq_sampler<<<NBLOCKS, THREADS, smem>>>(in0, h0, Wx, Wh, b, Wp, bp, (float*)d_out);
}

// round 6
// speedup vs baseline: 1.0982x; 1.0982x over previous
#include <cuda_runtime.h>
#include <stdint.h>
#include <math.h>

#define JAX_PARTITIONABLE 1

#define NROWS   65536
#define TSTEPS  12
#define WPB     8
#define THREADS 256
#define NBLOCKS 296        // 2 CTAs/SM on 148 SMs

// output layout (float32): seq | ent | logp | cnt | lengths | mask
#define OFF_ENT  (NROWS * TSTEPS)
#define OFF_LP   (2 * NROWS * TSTEPS)
#define OFF_CNT  (3 * NROWS * TSTEPS)
#define OFF_LEN  (OFF_CNT + NROWS)
#define OFF_MASK (OFF_LEN + NROWS)

// shared layout (float slots)
#define SM_WH    0          // 128x128 = 16384
#define SM_WPT   16384      // 16 x 132 (transposed Wp, padded) = 2112
#define SM_B     18496      // 128
#define SM_BP    18624      // 16
#define SM_H0    18640      // 128
#define SM_KEY   18768      // 24 u32
#define SM_HS    18792      // 8 warps * 8 rows * 128 = 8192   (16B aligned)
#define SM_SEQ   26984      // 8 warps * 8 * 12 int = 768
#define SM_ST    27752      // 8 warps * 8 * 8  int = 512
#define SM_TOTF  28264      // 113056 bytes -> 2 CTAs/SM fit

__device__ __forceinline__ uint32_t rotl32(uint32_t x, int n) {
    return (x << n) | (x >> (32 - n));
}

// Threefry-2x32, 20 rounds (exact JAX cipher)
__device__ __forceinline__ void tf2x32(uint32_t k0, uint32_t k1,
                                       uint32_t &x0, uint32_t &x1) {
    uint32_t k2 = k0 ^ k1 ^ 0x1BD11BDAu;
    x0 += k0; x1 += k1;
#define TFR(r) { x0 += x1; x1 = rotl32(x1, (r)); x1 ^= x0; }
    TFR(13) TFR(15) TFR(26) TFR(6)
    x0 += k1; x1 += k2 + 1u;
    TFR(17) TFR(29) TFR(16) TFR(24)
    x0 += k2; x1 += k0 + 2u;
    TFR(13) TFR(15) TFR(26) TFR(6)
    x0 += k0; x1 += k1 + 3u;
    TFR(17) TFR(29) TFR(16) TFR(24)
    x0 += k1; x1 += k2 + 4u;
    TFR(13) TFR(15) TFR(26) TFR(6)
    x0 += k2; x1 += k0 + 5u;
#undef TFR
}

__device__ __forceinline__ uint32_t gbits(uint32_t k0, uint32_t k1, uint32_t idx) {
#if JAX_PARTITIONABLE
    uint32_t a = 0u, b = idx;
    tf2x32(k0, k1, a, b);
    return a ^ b;
#else
    const uint32_t half = (uint32_t)(NROWS * 16) / 2u;
    if (idx < half) {
        uint32_t a = idx, b = idx + half;
        tf2x32(k0, k1, a, b);
        return a;
    } else {
        uint32_t a = idx - half, b = idx;
        tf2x32(k0, k1, a, b);
        return b;
    }
#endif
}

// Process one group of R rows through all 12 steps. R in {8, 4}.
template <int R>
__device__ __forceinline__ void run_group(
    int rowBase, float* __restrict__ sm, float4* __restrict__ hb4,
    int* __restrict__ seqw, int* __restrict__ stw,
    const float4* __restrict__ Wx4, float* __restrict__ out,
    int lane, int g, int tk,
    float4 xw0v, float4 bvecv, float4 hinit, float bpt)
{
    const int NS = R / 2;
    const float NEG_INF = __int_as_float(0xff800000);
    const uint32_t* keys = (const uint32_t*)(sm + SM_KEY);

    // ---- init group ----
#pragma unroll
    for (int r = 0; r < R; r++) hb4[r * 32 + lane] = hinit;
    if (lane < R) {
        int* st = stw + lane * 8;
        st[0] = 1; st[1] = 0; st[2] = 1; st[3] = 0; st[4] = 1; st[5] = -1; st[6] = -1;
        out[OFF_MASK + (size_t)(rowBase + lane) * 13] = 1.0f;
    }
    __syncwarp();

    for (int t = 0; t < TSTEPS; t++) {
        const uint32_t k0 = keys[2 * t];
        const uint32_t k1 = keys[2 * t + 1];

        // ---- acc init = x@Wx + b (one-hot Wx gather from global for t>0) ----
        float acc[R][4];
        if (t == 0) {
#pragma unroll
            for (int r = 0; r < R; r++) {
                acc[r][0] = xw0v.x + bvecv.x; acc[r][1] = xw0v.y + bvecv.y;
                acc[r][2] = xw0v.z + bvecv.z; acc[r][3] = xw0v.w + bvecv.w;
            }
        } else {
#pragma unroll
            for (int r = 0; r < R; r++) {
                int p0 = stw[r * 8 + 5];
                int p1 = stw[r * 8 + 6];
                float4 a = make_float4(0.f, 0.f, 0.f, 0.f);
                float4 c = make_float4(0.f, 0.f, 0.f, 0.f);
                if (p0 >= 0) a = __ldg(Wx4 + p0 * 32 + lane);
                if (p1 >= 0) c = __ldg(Wx4 + (16 + p1) * 32 + lane);
                acc[r][0] = a.x + c.x + bvecv.x;
                acc[r][1] = a.y + c.y + bvecv.y;
                acc[r][2] = a.z + c.z + bvecv.z;
                acc[r][3] = a.w + c.w + bvecv.w;
            }
        }

        // ---- h @ Wh : R rows, 4 outputs per lane ----
        {
            const float4* Wh4 = (const float4*)sm;  // SM_WH == 0
#pragma unroll 2
            for (int k4 = 0; k4 < 32; k4++) {
                float4 w0 = Wh4[(k4 * 4 + 0) * 32 + lane];
                float4 w1 = Wh4[(k4 * 4 + 1) * 32 + lane];
                float4 w2 = Wh4[(k4 * 4 + 2) * 32 + lane];
                float4 w3 = Wh4[(k4 * 4 + 3) * 32 + lane];
#pragma unroll
                for (int r = 0; r < R; r++) {
                    float4 hv = hb4[r * 32 + k4];
                    acc[r][0] = fmaf(hv.x, w0.x, acc[r][0]);
                    acc[r][1] = fmaf(hv.x, w0.y, acc[r][1]);
                    acc[r][2] = fmaf(hv.x, w0.z, acc[r][2]);
                    acc[r][3] = fmaf(hv.x, w0.w, acc[r][3]);
                    acc[r][0] = fmaf(hv.y, w1.x, acc[r][0]);
                    acc[r][1] = fmaf(hv.y, w1.y, acc[r][1]);
                    acc[r][2] = fmaf(hv.y, w1.z, acc[r][2]);
                    acc[r][3] = fmaf(hv.y, w1.w, acc[r][3]);
                    acc[r][0] = fmaf(hv.z, w2.x, acc[r][0]);
                    acc[r][1] = fmaf(hv.z, w2.y, acc[r][1]);
                    acc[r][2] = fmaf(hv.z, w2.z, acc[r][2]);
                    acc[r][3] = fmaf(hv.z, w2.w, acc[r][3]);
                    acc[r][0] = fmaf(hv.w, w3.x, acc[r][0]);
                    acc[r][1] = fmaf(hv.w, w3.y, acc[r][1]);
                    acc[r][2] = fmaf(hv.w, w3.z, acc[r][2]);
                    acc[r][3] = fmaf(hv.w, w3.w, acc[r][3]);
                }
            }
            __syncwarp();
#pragma unroll
            for (int r = 0; r < R; r++) {
                float4 hn;
                hn.x = tanhf(acc[r][0]);
                hn.y = tanhf(acc[r][1]);
                hn.z = tanhf(acc[r][2]);
                hn.w = tanhf(acc[r][3]);
                hb4[r * 32 + lane] = hn;
            }
            __syncwarp();
        }

        // ---- logits: lane = token tk, NS row-streams for half g ----
        float lg[NS];
        {
            float accl[NS];
#pragma unroll
            for (int s = 0; s < NS; s++) accl[s] = 0.f;
            const float4* WpT4 = (const float4*)(sm + SM_WPT);
#pragma unroll 4
            for (int k4 = 0; k4 < 32; k4++) {
                float4 wp = WpT4[tk * 33 + k4];
#pragma unroll
                for (int s = 0; s < NS; s++) {
                    float4 hv = hb4[(2 * s + g) * 32 + k4];
                    accl[s] = fmaf(hv.x, wp.x, accl[s]);
                    accl[s] = fmaf(hv.y, wp.y, accl[s]);
                    accl[s] = fmaf(hv.z, wp.z, accl[s]);
                    accl[s] = fmaf(hv.w, wp.w, accl[s]);
                }
            }
#pragma unroll
            for (int s = 0; s < NS; s++) lg[s] = accl[s] + bpt;
        }

        // ---- constraints (PRE-update state) ----
        bool ok[NS];
#pragma unroll
        for (int s = 0; s < NS; s++) {
            int r = 2 * s + g;
            int cnt = stw[r * 8 + 0], ln = stw[r * 8 + 1], hv = stw[r * 8 + 3];
            int cl = cnt + ln;
            bool o = true;
            if (tk >= 8 && cl < 2) o = false;
            if (tk <  8 && cl > TSTEPS - 2) o = false;
            if (tk == 8 && cnt == 1 && hv == 0) o = false;
            ok[s] = o;
        }

        // ---- exact two-stage softmax + mask + renorm ----
        float mx[NS];
#pragma unroll
        for (int s = 0; s < NS; s++) mx[s] = lg[s];
#pragma unroll
        for (int d = 1; d < 16; d <<= 1)
#pragma unroll
            for (int s = 0; s < NS; s++)
                mx[s] = fmaxf(mx[s], __shfl_xor_sync(0xffffffffu, mx[s], d));
        float ex[NS], z[NS];
#pragma unroll
        for (int s = 0; s < NS; s++) { ex[s] = expf(lg[s] - mx[s]); z[s] = ex[s]; }
#pragma unroll
        for (int d = 1; d < 16; d <<= 1)
#pragma unroll
            for (int s = 0; s < NS; s++)
                z[s] += __shfl_xor_sync(0xffffffffu, z[s], d);
        float pm[NS], ssum[NS];
#pragma unroll
        for (int s = 0; s < NS; s++) { pm[s] = ok[s] ? (ex[s] / z[s]) : 0.0f; ssum[s] = pm[s]; }
#pragma unroll
        for (int d = 1; d < 16; d <<= 1)
#pragma unroll
            for (int s = 0; s < NS; s++)
                ssum[s] += __shfl_xor_sync(0xffffffffu, ssum[s], d);
        float p[NS], logp[NS];
        bool pos[NS];
#pragma unroll
        for (int s = 0; s < NS; s++) {
            p[s] = pm[s] / ssum[s];
            pos[s] = p[s] > 0.0f;
            logp[s] = pos[s] ? logf(p[s]) : NEG_INF;
        }

        // ---- gumbel (exact threefry bits) + argmax ----
        float bs[NS];
        int bi[NS];
#pragma unroll
        for (int s = 0; s < NS; s++) {
            uint32_t idx = ((uint32_t)(rowBase + 2 * s + g)) * 16u + (uint32_t)tk;
            uint32_t bts = gbits(k0, k1, idx);
            float f = __uint_as_float((bts >> 9) | 0x3f800000u) - 1.0f;
            float u = (f == 0.0f) ? 1.17549435e-38f : f;
            float gu = -logf(-logf(u));
            bs[s] = pos[s] ? (logp[s] + gu) : NEG_INF;
            bi[s] = tk;
        }
#pragma unroll
        for (int d = 1; d < 16; d <<= 1) {
#pragma unroll
            for (int s = 0; s < NS; s++) {
                float os = __shfl_xor_sync(0xffffffffu, bs[s], d);
                int   oi = __shfl_xor_sync(0xffffffffu, bi[s], d);
                if (os > bs[s] || (os == bs[s] && oi < bi[s])) { bs[s] = os; bi[s] = oi; }
            }
        }

        // ---- entropy ----
        float et[NS];
#pragma unroll
        for (int s = 0; s < NS; s++) et[s] = pos[s] ? p[s] * logp[s] : 0.0f;
#pragma unroll
        for (int d = 1; d < 16; d <<= 1)
#pragma unroll
            for (int s = 0; s < NS; s++)
                et[s] += __shfl_xor_sync(0xffffffffu, et[s], d);

        // ---- logp at sampled token ----
        float lp[NS];
#pragma unroll
        for (int s = 0; s < NS; s++)
            lp[s] = __shfl_sync(0xffffffffu, logp[s], (lane & 16) + bi[s]);

        // ---- writer lanes: token/state/outputs (no ps scan here) ----
        if (tk == 0) {
#pragma unroll
            for (int s = 0; s < NS; s++) {
                int r   = 2 * s + g;
                int tok = bi[s];
                int* st = stw + r * 8;
                int row = rowBase + r;

                seqw[r * 12 + t] = tok;
                int ar  = (tok < 4) ? 2 : ((tok < 8) ? 1 : 0);
                int cnt = st[0] - 1 + ar;
                int ln  = st[1] + 1;
                int act = (cnt > 0) && st[2];
                st[0] = cnt; st[1] = ln; st[2] = act;
                st[3] = st[3] | (tok >= 9);
                st[4] += act;

                out[(size_t)row * 12 + t]                = (float)tok;
                out[OFF_ENT + (size_t)row * 12 + t]      = -et[s];
                out[OFF_LP  + (size_t)row * 12 + t]      = lp[s];
                out[OFF_MASK + (size_t)row * 13 + 1 + t] = act ? 1.0f : 0.0f;
            }
        }
        __syncwarp();

        // ---- parent/sibling scan, parallel across lanes 0..R-1 ----
        if (lane < R) {
            int r = lane;
            int tok = seqw[r * 12 + t];
            int ps0, ps1;
            if (tok < 8) {
                ps0 = tok; ps1 = -1;
            } else {
                ps0 = -1; ps1 = -1;
                int c = 0;
                bool found = false;
                for (int i = t; i >= 0; i--) {
                    int tk2 = seqw[r * 12 + i];
                    int a2 = (tk2 < 4) ? 2 : ((tk2 < 8) ? 1 : 0);
                    c += a2 - 1;
                    if (!found && c == 0) {
                        ps0 = tk2;
                        ps1 = (i + 1 < TSTEPS) ? seqw[r * 12 + i + 1] : -1;
                        found = true;
                    }
                }
            }
            stw[r * 8 + 5] = ps0;
            stw[r * 8 + 6] = ps1;
        }
        __syncwarp();
    }

    // ---- finalize group ----
    if (lane < R) {
        out[OFF_CNT + rowBase + lane] = (float)stw[lane * 8 + 0];
        out[OFF_LEN + rowBase + lane] = (float)stw[lane * 8 + 4];
    }
    __syncwarp();
}

__global__ void __launch_bounds__(THREADS, 2)
eq_sampler(const float* __restrict__ in0, const float* __restrict__ h0,
           const float* __restrict__ Wx, const float* __restrict__ Wh,
           const float* __restrict__ b,  const float* __restrict__ Wp,
           const float* __restrict__ bp, float* __restrict__ out) {
    extern __shared__ float sm[];
    int* smi = (int*)sm;
    const int tid = threadIdx.x;

    for (int i = tid; i < 16384; i += THREADS) sm[SM_WH + i] = Wh[i];
    // transposed, padded Wp: WpT[tok][k], stride 132
    for (int i = tid; i < 2048; i += THREADS) {
        int tok = i >> 7, k = i & 127;
        sm[SM_WPT + tok * 132 + k] = Wp[k * 16 + tok];
    }
    if (tid < 128) sm[SM_B  + tid] = b[tid];
    if (tid < 16)  sm[SM_BP + tid] = bp[tid];
    if (tid < 128) sm[SM_H0 + tid] = h0[tid];

    if (tid == 0) {
        uint32_t* kp = (uint32_t*)(sm + SM_KEY);
#if JAX_PARTITIONABLE
        for (int t = 0; t < TSTEPS; t++) {
            uint32_t a = 0u, bb = (uint32_t)t;
            tf2x32(0u, 42u, a, bb);
            kp[2 * t] = a; kp[2 * t + 1] = bb;
        }
#else
        uint32_t ov[24];
        for (int j = 0; j < 12; j++) {
            uint32_t a = (uint32_t)j, bb = (uint32_t)(j + 12);
            tf2x32(0u, 42u, a, bb);
            ov[j] = a; ov[12 + j] = bb;
        }
        for (int t = 0; t < TSTEPS; t++) { kp[2 * t] = ov[2 * t]; kp[2 * t + 1] = ov[2 * t + 1]; }
#endif
    }
    __syncthreads();

    const int wid  = tid >> 5;
    const int lane = tid & 31;
    const int g    = lane >> 4;
    const int tk   = lane & 15;

    float4* hb4 = (float4*)(sm + SM_HS + wid * 1024);   // 8 rows x 128
    int* seqw = smi + SM_SEQ + wid * 96;                // 8 rows x 12
    int* stw  = smi + SM_ST  + wid * 64;                // 8 rows x 8

    // t=0 input projection (identical for all rows) from global
    float4 xw0v;
    {
        float s0 = 0.f, s1 = 0.f, s2 = 0.f, s3 = 0.f;
#pragma unroll
        for (int k = 0; k < 32; k++) {
            float iv = __ldg(in0 + k);
            const float* wr = Wx + k * 128 + lane * 4;
            s0 = fmaf(iv, __ldg(wr + 0), s0);
            s1 = fmaf(iv, __ldg(wr + 1), s1);
            s2 = fmaf(iv, __ldg(wr + 2), s2);
            s3 = fmaf(iv, __ldg(wr + 3), s3);
        }
        xw0v = make_float4(s0, s1, s2, s3);
    }
    const float4 bvecv = ((const float4*)(sm + SM_B))[lane];
    const float4 hinit = ((const float4*)(sm + SM_H0))[lane];
    const float  bpt   = sm[SM_BP + tk];
    const float4* Wx4  = (const float4*)Wx;

    const int totalWarps = gridDim.x * WPB;
    const int gwid = blockIdx.x * WPB + wid;

    // main phase: R=8 groups, exactly (full8 / totalWarps) per warp
    const int full8 = NROWS / 8;                          // 8192
    const int base8 = (full8 / totalWarps) * totalWarps;  // 7104 @ grid 296
    for (int grp = gwid; grp < base8; grp += totalWarps)
        run_group<8>(grp * 8, sm, hb4, seqw, stw, Wx4, out,
                     lane, g, tk, xw0v, bvecv, hinit, bpt);

    // tail phase: remaining rows as R=4 groups (finer granularity -> balanced)
    const int tailRowBase = base8 * 8;
    const int tail4 = (NROWS - tailRowBase) / 4;          // 2176 @ grid 296
    for (int grp = gwid; grp < tail4; grp += totalWarps)
        run_group<4>(tailRowBase + grp * 4, sm, hb4, seqw, stw, Wx4, out,
                     lane, g, tk, xw0v, bvecv, hinit, bpt);
}

extern "C" void kernel_launch(void* const* d_in, const int* in_sizes, int n_in,
                              void* d_out, int out_size) {
    int base = (in_sizes[0] == 1) ? 1 : 0;
    const float* in0 = (const float*)d_in[base + 0];
    const float* h0  = (const float*)d_in[base + 1];
    const float* Wx  = (const float*)d_in[base + 2];
    const float* Wh  = (const float*)d_in[base + 3];
    const float* b   = (const float*)d_in[base + 4];
    const float* Wp  = (const float*)d_in[base + 5];
    const float* bp  = (const float*)d_in[base + 6];

    size_t smem = (size_t)SM_TOTF * sizeof(float);
    cudaFuncSetAttribute(eq_sampler, cudaFuncAttributeMaxDynamicSharedMemorySize, (int)smem);
    eq_sampler<<<NBLOCKS, THREADS, smem>>>(in0, h0, Wx, Wh, b, Wp, bp, (float*)d_out);
}

// round 7
// speedup vs baseline: 1.2503x; 1.1385x over previous
#include <cuda_runtime.h>
#include <stdint.h>
#include <math.h>

#define JAX_PARTITIONABLE 1

#define NROWS   65536
#define TSTEPS  12
#define WPB     8
#define THREADS 256
#define NBLOCKS 296        // 2 CTAs/SM on 148 SMs

// output layout (float32): seq | ent | logp | cnt | lengths | mask
#define OFF_ENT  (NROWS * TSTEPS)
#define OFF_LP   (2 * NROWS * TSTEPS)
#define OFF_CNT  (3 * NROWS * TSTEPS)
#define OFF_LEN  (OFF_CNT + NROWS)
#define OFF_MASK (OFF_LEN + NROWS)

// shared layout (float slots)
#define SM_WH    0          // 128x128 = 16384
#define SM_WPT   16384      // 16 x 132 (transposed Wp, padded) = 2112
#define SM_B     18496      // 128
#define SM_BP    18624      // 16
#define SM_H0    18640      // 128
#define SM_KEY   18768      // 24 u32
#define SM_HS    18792      // 8 warps * 4 pairs * 128 float2 = 8192 floats (16B aligned)
#define SM_SEQ   26984      // 8 warps * 8 * 12 int = 768
#define SM_ST    27752      // 8 warps * 8 * 8  int = 512
#define SM_TOTF  28264      // 113056 bytes -> 2 CTAs/SM fit

typedef unsigned long long u64t;

__device__ __forceinline__ u64t pk2(float lo, float hi) {
    u64t r;
    asm("mov.b64 %0, {%1, %2};" : "=l"(r) : "f"(lo), "f"(hi));
    return r;
}
__device__ __forceinline__ u64t pkdup(float v) { return pk2(v, v); }
__device__ __forceinline__ void upk2(u64t x, float& lo, float& hi) {
    asm("mov.b64 {%0, %1}, %2;" : "=f"(lo), "=f"(hi) : "l"(x));
}
// packed dual-fp32 FMA (Blackwell): lo/hi halves are independent fp32 FMAs
__device__ __forceinline__ u64t fma2(u64t a, u64t b, u64t c) {
    u64t d;
    asm("fma.rn.f32x2 %0, %1, %2, %3;" : "=l"(d) : "l"(a), "l"(b), "l"(c));
    return d;
}

__device__ __forceinline__ uint32_t rotl32(uint32_t x, int n) {
    return (x << n) | (x >> (32 - n));
}

// Threefry-2x32, 20 rounds (exact JAX cipher)
__device__ __forceinline__ void tf2x32(uint32_t k0, uint32_t k1,
                                       uint32_t &x0, uint32_t &x1) {
    uint32_t k2 = k0 ^ k1 ^ 0x1BD11BDAu;
    x0 += k0; x1 += k1;
#define TFR(r) { x0 += x1; x1 = rotl32(x1, (r)); x1 ^= x0; }
    TFR(13) TFR(15) TFR(26) TFR(6)
    x0 += k1; x1 += k2 + 1u;
    TFR(17) TFR(29) TFR(16) TFR(24)
    x0 += k2; x1 += k0 + 2u;
    TFR(13) TFR(15) TFR(26) TFR(6)
    x0 += k0; x1 += k1 + 3u;
    TFR(17) TFR(29) TFR(16) TFR(24)
    x0 += k1; x1 += k2 + 4u;
    TFR(13) TFR(15) TFR(26) TFR(6)
    x0 += k2; x1 += k0 + 5u;
#undef TFR
}

__device__ __forceinline__ uint32_t gbits(uint32_t k0, uint32_t k1, uint32_t idx) {
#if JAX_PARTITIONABLE
    uint32_t a = 0u, b = idx;
    tf2x32(k0, k1, a, b);
    return a ^ b;
#else
    const uint32_t half = (uint32_t)(NROWS * 16) / 2u;
    if (idx < half) {
        uint32_t a = idx, b = idx + half;
        tf2x32(k0, k1, a, b);
        return a;
    } else {
        uint32_t a = idx - half, b = idx;
        tf2x32(k0, k1, a, b);
        return b;
    }
#endif
}

// Process one group of R rows (R even, R/2 row-pairs). h stored pair-interleaved:
// hw[pair*128 + k] = (h_{2*pair}[k], h_{2*pair+1}[k]) as packed f32x2.
template <int R>
__device__ __forceinline__ void run_group(
    int rowBase, float* __restrict__ sm, u64t* __restrict__ hw,
    int* __restrict__ seqw, int* __restrict__ stw,
    const float4* __restrict__ Wx4, float* __restrict__ out,
    int lane, int g, int tk,
    const u64t* __restrict__ ivd,    // 4: dup(xw0+b) per col (t==0 init)
    float4 bvecv, u64t hinit0, u64t hinit1, u64t hinit2, u64t hinit3,
    float bpt)
{
    constexpr int NP = R / 2;     // row pairs
    constexpr int PH = R / 4;     // pairs per half-warp
    constexpr int SS = R / 2;     // scalar sampler streams per half
    const float NEG_INF = __int_as_float(0xff800000);
    const uint32_t* keys = (const uint32_t*)(sm + SM_KEY);

    // ---- init group ----
#pragma unroll
    for (int p = 0; p < NP; p++) {
        u64t* pw = hw + p * 128 + lane * 4;
        pw[0] = hinit0; pw[1] = hinit1; pw[2] = hinit2; pw[3] = hinit3;
    }
    if (lane < R) {
        int* st = stw + lane * 8;
        st[0] = 1; st[1] = 0; st[2] = 1; st[3] = 0; st[4] = 1; st[5] = -1; st[6] = -1;
        out[OFF_MASK + (size_t)(rowBase + lane) * 13] = 1.0f;
    }
    __syncwarp();

    for (int t = 0; t < TSTEPS; t++) {
        const uint32_t k0 = keys[2 * t];
        const uint32_t k1 = keys[2 * t + 1];

        // ---- acc2 init = pack(x@Wx + b) per pair ----
        u64t acc2[NP][4];
        if (t == 0) {
#pragma unroll
            for (int p = 0; p < NP; p++) {
                acc2[p][0] = ivd[0]; acc2[p][1] = ivd[1];
                acc2[p][2] = ivd[2]; acc2[p][3] = ivd[3];
            }
        } else {
#pragma unroll
            for (int p = 0; p < NP; p++) {
                int p0a = stw[(2 * p) * 8 + 5],     p1a = stw[(2 * p) * 8 + 6];
                int p0b = stw[(2 * p + 1) * 8 + 5], p1b = stw[(2 * p + 1) * 8 + 6];
                float4 a0 = make_float4(0.f, 0.f, 0.f, 0.f), c0 = a0, a1 = a0, c1 = a0;
                if (p0a >= 0) a0 = __ldg(Wx4 + p0a * 32 + lane);
                if (p1a >= 0) c0 = __ldg(Wx4 + (16 + p1a) * 32 + lane);
                if (p0b >= 0) a1 = __ldg(Wx4 + p0b * 32 + lane);
                if (p1b >= 0) c1 = __ldg(Wx4 + (16 + p1b) * 32 + lane);
                acc2[p][0] = pk2(a0.x + c0.x + bvecv.x, a1.x + c1.x + bvecv.x);
                acc2[p][1] = pk2(a0.y + c0.y + bvecv.y, a1.y + c1.y + bvecv.y);
                acc2[p][2] = pk2(a0.z + c0.z + bvecv.z, a1.z + c1.z + bvecv.z);
                acc2[p][3] = pk2(a0.w + c0.w + bvecv.w, a1.w + c1.w + bvecv.w);
            }
        }

        // ---- h @ Wh with packed FFMA2: NP pairs, 4 output cols per lane ----
        {
            const float4* Wh4 = (const float4*)sm;  // SM_WH == 0
#pragma unroll 1
            for (int k4 = 0; k4 < 32; k4++) {
                u64t hk[NP][4];
#pragma unroll
                for (int p = 0; p < NP; p++) {
                    const u64t* ph = hw + p * 128 + 4 * k4;
                    hk[p][0] = ph[0]; hk[p][1] = ph[1];
                    hk[p][2] = ph[2]; hk[p][3] = ph[3];
                }
#pragma unroll
                for (int kk = 0; kk < 4; kk++) {
                    float4 w = Wh4[(k4 * 4 + kk) * 32 + lane];
                    u64t wd0 = pkdup(w.x), wd1 = pkdup(w.y);
                    u64t wd2 = pkdup(w.z), wd3 = pkdup(w.w);
#pragma unroll
                    for (int p = 0; p < NP; p++) {
                        acc2[p][0] = fma2(hk[p][kk], wd0, acc2[p][0]);
                        acc2[p][1] = fma2(hk[p][kk], wd1, acc2[p][1]);
                        acc2[p][2] = fma2(hk[p][kk], wd2, acc2[p][2]);
                        acc2[p][3] = fma2(hk[p][kk], wd3, acc2[p][3]);
                    }
                }
            }
            __syncwarp();
            // h_new = tanh(acc) ; store back pair-interleaved
#pragma unroll
            for (int p = 0; p < NP; p++) {
                u64t* pw = hw + p * 128 + lane * 4;
#pragma unroll
                for (int v = 0; v < 4; v++) {
                    float lo, hi;
                    upk2(acc2[p][v], lo, hi);
                    pw[v] = pk2(tanhf(lo), tanhf(hi));
                }
            }
            __syncwarp();
        }

        // ---- logits: lane = token tk; PH pairs for this half ----
        float lg[SS];
        {
            u64t accl2[PH];
#pragma unroll
            for (int q = 0; q < PH; q++) accl2[q] = 0ull;
            const float4* WpT4 = (const float4*)(sm + SM_WPT);
#pragma unroll 4
            for (int k4 = 0; k4 < 32; k4++) {
                float4 wp = WpT4[tk * 33 + k4];
                u64t wd0 = pkdup(wp.x), wd1 = pkdup(wp.y);
                u64t wd2 = pkdup(wp.z), wd3 = pkdup(wp.w);
#pragma unroll
                for (int q = 0; q < PH; q++) {
                    const u64t* ph = hw + (g + 2 * q) * 128 + 4 * k4;
                    accl2[q] = fma2(ph[0], wd0, accl2[q]);
                    accl2[q] = fma2(ph[1], wd1, accl2[q]);
                    accl2[q] = fma2(ph[2], wd2, accl2[q]);
                    accl2[q] = fma2(ph[3], wd3, accl2[q]);
                }
            }
#pragma unroll
            for (int q = 0; q < PH; q++) {
                float lo, hi;
                upk2(accl2[q], lo, hi);
                lg[2 * q]     = lo + bpt;
                lg[2 * q + 1] = hi + bpt;
            }
        }

        // stream s' -> row r = 2*(g + 2*(s'>>1)) + (s'&1)
        int rmap[SS];
#pragma unroll
        for (int s = 0; s < SS; s++) rmap[s] = 2 * (g + 2 * (s >> 1)) + (s & 1);

        // ---- constraints (PRE-update state) ----
        bool ok[SS];
#pragma unroll
        for (int s = 0; s < SS; s++) {
            int r = rmap[s];
            int cnt = stw[r * 8 + 0], ln = stw[r * 8 + 1], hv = stw[r * 8 + 3];
            int cl = cnt + ln;
            bool o = true;
            if (tk >= 8 && cl < 2) o = false;
            if (tk <  8 && cl > TSTEPS - 2) o = false;
            if (tk == 8 && cnt == 1 && hv == 0) o = false;
            ok[s] = o;
        }

        // ---- exact two-stage softmax + mask + renorm (16-lane reductions) ----
        float mx[SS];
#pragma unroll
        for (int s = 0; s < SS; s++) mx[s] = lg[s];
#pragma unroll
        for (int d = 1; d < 16; d <<= 1)
#pragma unroll
            for (int s = 0; s < SS; s++)
                mx[s] = fmaxf(mx[s], __shfl_xor_sync(0xffffffffu, mx[s], d));
        float ex[SS], z[SS];
#pragma unroll
        for (int s = 0; s < SS; s++) { ex[s] = expf(lg[s] - mx[s]); z[s] = ex[s]; }
#pragma unroll
        for (int d = 1; d < 16; d <<= 1)
#pragma unroll
            for (int s = 0; s < SS; s++)
                z[s] += __shfl_xor_sync(0xffffffffu, z[s], d);
        float pm[SS], ssum[SS];
#pragma unroll
        for (int s = 0; s < SS; s++) { pm[s] = ok[s] ? (ex[s] / z[s]) : 0.0f; ssum[s] = pm[s]; }
#pragma unroll
        for (int d = 1; d < 16; d <<= 1)
#pragma unroll
            for (int s = 0; s < SS; s++)
                ssum[s] += __shfl_xor_sync(0xffffffffu, ssum[s], d);
        float p[SS], logp[SS];
        bool pos[SS];
#pragma unroll
        for (int s = 0; s < SS; s++) {
            p[s] = pm[s] / ssum[s];
            pos[s] = p[s] > 0.0f;
            logp[s] = pos[s] ? logf(p[s]) : NEG_INF;
        }

        // ---- gumbel (exact threefry bits) + argmax ----
        float bs[SS];
        int bi[SS];
#pragma unroll
        for (int s = 0; s < SS; s++) {
            uint32_t idx = ((uint32_t)(rowBase + rmap[s])) * 16u + (uint32_t)tk;
            uint32_t bts = gbits(k0, k1, idx);
            float f = __uint_as_float((bts >> 9) | 0x3f800000u) - 1.0f;
            float u = (f == 0.0f) ? 1.17549435e-38f : f;
            float gu = -logf(-logf(u));
            bs[s] = pos[s] ? (logp[s] + gu) : NEG_INF;
            bi[s] = tk;
        }
#pragma unroll
        for (int d = 1; d < 16; d <<= 1) {
#pragma unroll
            for (int s = 0; s < SS; s++) {
                float os = __shfl_xor_sync(0xffffffffu, bs[s], d);
                int   oi = __shfl_xor_sync(0xffffffffu, bi[s], d);
                if (os > bs[s] || (os == bs[s] && oi < bi[s])) { bs[s] = os; bi[s] = oi; }
            }
        }

        // ---- entropy ----
        float et[SS];
#pragma unroll
        for (int s = 0; s < SS; s++) et[s] = pos[s] ? p[s] * logp[s] : 0.0f;
#pragma unroll
        for (int d = 1; d < 16; d <<= 1)
#pragma unroll
            for (int s = 0; s < SS; s++)
                et[s] += __shfl_xor_sync(0xffffffffu, et[s], d);

        // ---- logp at sampled token ----
        float lp[SS];
#pragma unroll
        for (int s = 0; s < SS; s++)
            lp[s] = __shfl_sync(0xffffffffu, logp[s], (lane & 16) + bi[s]);

        // ---- writer lanes: token/state/outputs ----
        if (tk == 0) {
#pragma unroll
            for (int s = 0; s < SS; s++) {
                int r   = rmap[s];
                int tok = bi[s];
                int* st = stw + r * 8;
                int row = rowBase + r;

                seqw[r * 12 + t] = tok;
                int ar  = (tok < 4) ? 2 : ((tok < 8) ? 1 : 0);
                int cnt = st[0] - 1 + ar;
                int ln  = st[1] + 1;
                int act = (cnt > 0) && st[2];
                st[0] = cnt; st[1] = ln; st[2] = act;
                st[3] = st[3] | (tok >= 9);
                st[4] += act;

                out[(size_t)row * 12 + t]                = (float)tok;
                out[OFF_ENT + (size_t)row * 12 + t]      = -et[s];
                out[OFF_LP  + (size_t)row * 12 + t]      = lp[s];
                out[OFF_MASK + (size_t)row * 13 + 1 + t] = act ? 1.0f : 0.0f;
            }
        }
        __syncwarp();

        // ---- parent/sibling scan, parallel across lanes 0..R-1 ----
        if (lane < R) {
            int r = lane;
            int tok = seqw[r * 12 + t];
            int ps0, ps1;
            if (tok < 8) {
                ps0 = tok; ps1 = -1;
            } else {
                ps0 = -1; ps1 = -1;
                int c = 0;
                bool found = false;
                for (int i = t; i >= 0; i--) {
                    int tk2 = seqw[r * 12 + i];
                    int a2 = (tk2 < 4) ? 2 : ((tk2 < 8) ? 1 : 0);
                    c += a2 - 1;
                    if (!found && c == 0) {
                        ps0 = tk2;
                        ps1 = (i + 1 < TSTEPS) ? seqw[r * 12 + i + 1] : -1;
                        found = true;
                    }
                }
            }
            stw[r * 8 + 5] = ps0;
            stw[r * 8 + 6] = ps1;
        }
        __syncwarp();
    }

    // ---- finalize group ----
    if (lane < R) {
        out[OFF_CNT + rowBase + lane] = (float)stw[lane * 8 + 0];
        out[OFF_LEN + rowBase + lane] = (float)stw[lane * 8 + 4];
    }
    __syncwarp();
}

__global__ void __launch_bounds__(THREADS, 2)
eq_sampler(const float* __restrict__ in0, const float* __restrict__ h0,
           const float* __restrict__ Wx, const float* __restrict__ Wh,
           const float* __restrict__ b,  const float* __restrict__ Wp,
           const float* __restrict__ bp, float* __restrict__ out) {
    extern __shared__ float sm[];
    int* smi = (int*)sm;
    const int tid = threadIdx.x;

    for (int i = tid; i < 16384; i += THREADS) sm[SM_WH + i] = Wh[i];
    // transposed, padded Wp: WpT[tok][k], stride 132
    for (int i = tid; i < 2048; i += THREADS) {
        int tok = i >> 7, k = i & 127;
        sm[SM_WPT + tok * 132 + k] = Wp[k * 16 + tok];
    }
    if (tid < 128) sm[SM_B  + tid] = b[tid];
    if (tid < 16)  sm[SM_BP + tid] = bp[tid];
    if (tid < 128) sm[SM_H0 + tid] = h0[tid];

    if (tid == 0) {
        uint32_t* kp = (uint32_t*)(sm + SM_KEY);
#if JAX_PARTITIONABLE
        for (int t = 0; t < TSTEPS; t++) {
            uint32_t a = 0u, bb = (uint32_t)t;
            tf2x32(0u, 42u, a, bb);
            kp[2 * t] = a; kp[2 * t + 1] = bb;
        }
#else
        uint32_t ov[24];
        for (int j = 0; j < 12; j++) {
            uint32_t a = (uint32_t)j, bb = (uint32_t)(j + 12);
            tf2x32(0u, 42u, a, bb);
            ov[j] = a; ov[12 + j] = bb;
        }
        for (int t = 0; t < TSTEPS; t++) { kp[2 * t] = ov[2 * t]; kp[2 * t + 1] = ov[2 * t + 1]; }
#endif
    }
    __syncthreads();

    const int wid  = tid >> 5;
    const int lane = tid & 31;
    const int g    = lane >> 4;
    const int tk   = lane & 15;

    u64t* hw  = (u64t*)(sm + SM_HS) + wid * 512;        // 4 pairs x 128 packed f32x2
    int* seqw = smi + SM_SEQ + wid * 96;                // 8 rows x 12
    int* stw  = smi + SM_ST  + wid * 64;                // 8 rows x 8

    // t=0 input projection (identical for all rows) from global
    float4 xw0v;
    {
        float s0 = 0.f, s1 = 0.f, s2 = 0.f, s3 = 0.f;
#pragma unroll
        for (int k = 0; k < 32; k++) {
            float iv = __ldg(in0 + k);
            const float* wr = Wx + k * 128 + lane * 4;
            s0 = fmaf(iv, __ldg(wr + 0), s0);
            s1 = fmaf(iv, __ldg(wr + 1), s1);
            s2 = fmaf(iv, __ldg(wr + 2), s2);
            s3 = fmaf(iv, __ldg(wr + 3), s3);
        }
        xw0v = make_float4(s0, s1, s2, s3);
    }
    const float4 bvecv = ((const float4*)(sm + SM_B))[lane];
    const float4 hinit = ((const float4*)(sm + SM_H0))[lane];
    const float  bpt   = sm[SM_BP + tk];
    const float4* Wx4  = (const float4*)Wx;

    u64t ivd[4];
    ivd[0] = pkdup(xw0v.x + bvecv.x);
    ivd[1] = pkdup(xw0v.y + bvecv.y);
    ivd[2] = pkdup(xw0v.z + bvecv.z);
    ivd[3] = pkdup(xw0v.w + bvecv.w);
    const u64t hi0 = pkdup(hinit.x), hi1 = pkdup(hinit.y);
    const u64t hi2 = pkdup(hinit.z), hi3 = pkdup(hinit.w);

    const int totalWarps = gridDim.x * WPB;
    const int gwid = blockIdx.x * WPB + wid;

    // main phase: R=8 groups, exactly (full8 / totalWarps) per warp
    const int full8 = NROWS / 8;
    const int base8 = (full8 / totalWarps) * totalWarps;
    for (int grp = gwid; grp < base8; grp += totalWarps)
        run_group<8>(grp * 8, sm, hw, seqw, stw, Wx4, out,
                     lane, g, tk, ivd, bvecv, hi0, hi1, hi2, hi3, bpt);

    // tail phase: remaining rows as R=4 groups
    const int tailRowBase = base8 * 8;
    const int tail4 = (NROWS - tailRowBase) / 4;
    for (int grp = gwid; grp < tail4; grp += totalWarps)
        run_group<4>(tailRowBase + grp * 4, sm, hw, seqw, stw, Wx4, out,
                     lane, g, tk, ivd, bvecv, hi0, hi1, hi2, hi3, bpt);
}

extern "C" void kernel_launch(void* const* d_in, const int* in_sizes, int n_in,
                              void* d_out, int out_size) {
    int base = (in_sizes[0] == 1) ? 1 : 0;
    const float* in0 = (const float*)d_in[base + 0];
    const float* h0  = (const float*)d_in[base + 1];
    const float* Wx  = (const float*)d_in[base + 2];
    const float* Wh  = (const float*)d_in[base + 3];
    const float* b   = (const float*)d_in[base + 4];
    const float* Wp  = (const float*)d_in[base + 5];
    const float* bp  = (const float*)d_in[base + 6];

    size_t smem = (size_t)SM_TOTF * sizeof(float);
    cudaFuncSetAttribute(eq_sampler, cudaFuncAttributeMaxDynamicSharedMemorySize, (int)smem);
    eq_sampler<<<NBLOCKS, THREADS, smem>>>(in0, h0, Wx, Wh, b, Wp, bp, (float*)d_out);
}